// round 6
// baseline (speedup 1.0000x reference)
#include <cuda_runtime.h>
#include <math.h>
#include <stdint.h>

#define NTOK 32768
#define NE   64
#define NKTOP 8

// ===========================================================================
// scratch (device globals: allocation-free)
// ===========================================================================
__device__ __align__(16) float g_h1[(size_t)NTOK * 2048];
__device__ __align__(16) float g_h2[(size_t)NTOK * 2048];
__device__ __align__(16) float g_h4[(size_t)NTOK * 1024];
__device__ __align__(16) float g_logits [(size_t)NTOK * NE];
__device__ __align__(16) float g_nlogits[(size_t)NTOK * NE];

// ===========================================================================
// tf32 split-MMA GEMM: C[N,M] = relu(A[N,K] @ W[K,M] + bias)
// - mma.sync.m16n8k8 tf32 (base ISA, compiles for plain sm_103 target)
// - fp32 accuracy via 2-way tf32 split, 3 products (hh, hl, lh), err ~2^-22
// - Split done ONCE at smem-fill time -> hot loop is pure LDS + HMMA
// - CTA 128x128, K-chunk 32, double-buffered hi/lo smem, reg-staged prefetch
// ===========================================================================
#define A_STRIDE 36            // 32 + 4 pad: A-frag bank == lane (conflict-free)
#define B_STRIDE 136           // 128 + 8 pad: B-frag banks 8*tig+g (conflict-free)
#define A_SZ (128 * A_STRIDE)  // floats, one split half
#define B_SZ (32 * B_STRIDE)
#define HALF_SZ (A_SZ + A_SZ + B_SZ + B_SZ)       // Ah+Al+Bh+Bl per buffer
#define SMEM_BYTES (2 * HALF_SZ * 4)              // double buffered: 143,360 B

__device__ __forceinline__ float tf32r(float x) {
    uint32_t h;
    asm("cvt.rna.tf32.f32 %0, %1;" : "=r"(h) : "f"(x));
    return __uint_as_float(h);
}

__device__ __forceinline__ void mma8(float* c, const uint32_t* a, const uint32_t* b) {
    asm volatile(
        "mma.sync.aligned.m16n8k8.row.col.f32.tf32.tf32.f32 "
        "{%0,%1,%2,%3}, {%4,%5,%6,%7}, {%8,%9}, {%0,%1,%2,%3};"
        : "+f"(c[0]), "+f"(c[1]), "+f"(c[2]), "+f"(c[3])
        : "r"(a[0]), "r"(a[1]), "r"(a[2]), "r"(a[3]), "r"(b[0]), "r"(b[1]));
}

__global__ __launch_bounds__(256, 1)
void mm_tf32(const float* __restrict__ A, const float* __restrict__ B,
             const float* __restrict__ bias, float* __restrict__ C,
             int K, int M)
{
    extern __shared__ __align__(16) float sm[];
    // buffer layout: [Ah | Al | Bh | Bl] x2
    float* Ah[2] = {sm,                      sm + HALF_SZ};
    float* Al[2] = {Ah[0] + A_SZ,            Ah[1] + A_SZ};
    float* Bh[2] = {Al[0] + A_SZ,            Al[1] + A_SZ};
    float* Bl[2] = {Bh[0] + B_SZ,            Bh[1] + B_SZ};

    const int tid  = threadIdx.x;
    const int lane = tid & 31;
    const int wid  = tid >> 5;
    const int row0 = blockIdx.y << 7;
    const int col0 = blockIdx.x << 7;
    const int wm   = (wid & 1) << 6;   // warp m-offset: 0 / 64
    const int wn   = (wid >> 1) << 5;  // warp n-offset: 0 / 32 / 64 / 96
    const int g    = lane >> 2;        // 0..7
    const int tig  = lane & 3;         // 0..3

    // global-load mapping (A tile 128x32, B tile 32x128: 4 float4 each/thread)
    const int arow = tid >> 3;          // + 32*i
    const int aj   = (tid & 7) << 2;
    const int brow = tid >> 5;          // + 8*i
    const int bj   = (tid & 31) << 2;

    float4 ra[4], rb[4];
    float c[4][4][4];
#pragma unroll
    for (int mt = 0; mt < 4; ++mt)
#pragma unroll
        for (int nt = 0; nt < 4; ++nt)
#pragma unroll
            for (int e = 0; e < 4; ++e) c[mt][nt][e] = 0.f;

    const int nk = K >> 5;

    // ---- fill helper (split hi/lo at store time) ----
    auto store_split = [&](int buf) {
#pragma unroll
        for (int i = 0; i < 4; ++i) {
            float4 h, l;
            h.x = tf32r(ra[i].x); l.x = tf32r(ra[i].x - h.x);
            h.y = tf32r(ra[i].y); l.y = tf32r(ra[i].y - h.y);
            h.z = tf32r(ra[i].z); l.z = tf32r(ra[i].z - h.z);
            h.w = tf32r(ra[i].w); l.w = tf32r(ra[i].w - h.w);
            *(float4*)(Ah[buf] + (arow + 32 * i) * A_STRIDE + aj) = h;
            *(float4*)(Al[buf] + (arow + 32 * i) * A_STRIDE + aj) = l;
            h.x = tf32r(rb[i].x); l.x = tf32r(rb[i].x - h.x);
            h.y = tf32r(rb[i].y); l.y = tf32r(rb[i].y - h.y);
            h.z = tf32r(rb[i].z); l.z = tf32r(rb[i].z - h.z);
            h.w = tf32r(rb[i].w); l.w = tf32r(rb[i].w - h.w);
            *(float4*)(Bh[buf] + (brow + 8 * i) * B_STRIDE + bj) = h;
            *(float4*)(Bl[buf] + (brow + 8 * i) * B_STRIDE + bj) = l;
        }
    };

    // prologue: chunk 0 -> regs -> smem buf 0
#pragma unroll
    for (int i = 0; i < 4; ++i) {
        ra[i] = *(const float4*)(A + (size_t)(row0 + arow + 32 * i) * K + aj);
        rb[i] = *(const float4*)(B + (size_t)(brow + 8 * i) * M + col0 + bj);
    }
    store_split(0);
    __syncthreads();

    for (int t = 0; t < nk; ++t) {
        const int cur = t & 1;
        const bool hasNext = (t + 1) < nk;
        if (hasNext) {
            const int kc = (t + 1) << 5;
#pragma unroll
            for (int i = 0; i < 4; ++i) {
                ra[i] = *(const float4*)(A + (size_t)(row0 + arow + 32 * i) * K + kc + aj);
                rb[i] = *(const float4*)(B + (size_t)(kc + brow + 8 * i) * M + col0 + bj);
            }
        }

        const float* Ahp = Ah[cur];
        const float* Alp = Al[cur];
        const float* Bhp = Bh[cur];
        const float* Blp = Bl[cur];
#pragma unroll
        for (int k8 = 0; k8 < 4; ++k8) {
            // B fragments (4 n-tiles), hi + lo — pure LDS
            uint32_t bh[4][2], bl[4][2];
#pragma unroll
            for (int nt = 0; nt < 4; ++nt) {
                const int o = (k8 * 8 + tig) * B_STRIDE + wn + nt * 8 + g;
                bh[nt][0] = __float_as_uint(Bhp[o]);
                bh[nt][1] = __float_as_uint(Bhp[o + 4 * B_STRIDE]);
                bl[nt][0] = __float_as_uint(Blp[o]);
                bl[nt][1] = __float_as_uint(Blp[o + 4 * B_STRIDE]);
            }
#pragma unroll
            for (int mt = 0; mt < 4; ++mt) {
                const int o = (wm + mt * 16 + g) * A_STRIDE + k8 * 8 + tig;
                uint32_t ah[4], al[4];
                ah[0] = __float_as_uint(Ahp[o]);
                ah[1] = __float_as_uint(Ahp[o + 8 * A_STRIDE]);
                ah[2] = __float_as_uint(Ahp[o + 4]);
                ah[3] = __float_as_uint(Ahp[o + 8 * A_STRIDE + 4]);
                al[0] = __float_as_uint(Alp[o]);
                al[1] = __float_as_uint(Alp[o + 8 * A_STRIDE]);
                al[2] = __float_as_uint(Alp[o + 4]);
                al[3] = __float_as_uint(Alp[o + 8 * A_STRIDE + 4]);
                // nt-inner: 4 independent accumulator chains
#pragma unroll
                for (int nt = 0; nt < 4; ++nt) mma8(c[mt][nt], ah, bh[nt]);
#pragma unroll
                for (int nt = 0; nt < 4; ++nt) mma8(c[mt][nt], ah, bl[nt]);
#pragma unroll
                for (int nt = 0; nt < 4; ++nt) mma8(c[mt][nt], al, bh[nt]);
            }
        }

        if (hasNext) store_split(cur ^ 1);
        __syncthreads();
    }

    // epilogue: bias + ReLU, float2 stores
#pragma unroll
    for (int mt = 0; mt < 4; ++mt) {
        const int r = row0 + wm + mt * 16 + g;
#pragma unroll
        for (int nt = 0; nt < 4; ++nt) {
            const int cc = col0 + wn + nt * 8 + 2 * tig;
            const float b0 = bias[cc], b1 = bias[cc + 1];
            float2 v0, v1;
            v0.x = fmaxf(c[mt][nt][0] + b0, 0.f);
            v0.y = fmaxf(c[mt][nt][1] + b1, 0.f);
            v1.x = fmaxf(c[mt][nt][2] + b0, 0.f);
            v1.y = fmaxf(c[mt][nt][3] + b1, 0.f);
            *(float2*)(C + (size_t)r * M + cc)       = v0;
            *(float2*)(C + (size_t)(r + 8) * M + cc) = v1;
        }
    }
}

// ---------------------------------------------------------------------------
// Narrow fp32 GEMM: C[N,64] = A[N,K] @ B[K,64] + bias (tiny share of time)
// ---------------------------------------------------------------------------
__global__ __launch_bounds__(256)
void gemm64_bias_k(const float* __restrict__ A, const float* __restrict__ B,
                   const float* __restrict__ bias, float* __restrict__ C, int K)
{
    __shared__ __align__(16) float As[16][128];
    __shared__ __align__(16) float Bsm[16][64];

    const int tid  = threadIdx.x;
    const int row0 = blockIdx.x << 7;
    const int tx   = tid & 15;
    const int ty   = tid >> 4;
    const int aRow = tid >> 2;
    const int aCol = (tid & 3) << 2;
    const int bRow = tid >> 4;
    const int bCol = (tid & 15) << 2;

    float acc[8][4];
#pragma unroll
    for (int i = 0; i < 8; ++i)
#pragma unroll
        for (int j = 0; j < 4; ++j) acc[i][j] = 0.f;

    const int nk = K >> 4;
    for (int t = 0; t < nk; ++t) {
        const int k0 = t << 4;
        float4 a0 = *(const float4*)&A[(size_t)(row0 + aRow)      * K + k0 + aCol];
        float4 a1 = *(const float4*)&A[(size_t)(row0 + aRow + 64) * K + k0 + aCol];
        float4 b0 = *(const float4*)&B[(size_t)(k0 + bRow) * 64 + bCol];
        __syncthreads();
        As[aCol + 0][aRow]      = a0.x; As[aCol + 1][aRow]      = a0.y;
        As[aCol + 2][aRow]      = a0.z; As[aCol + 3][aRow]      = a0.w;
        As[aCol + 0][aRow + 64] = a1.x; As[aCol + 1][aRow + 64] = a1.y;
        As[aCol + 2][aRow + 64] = a1.z; As[aCol + 3][aRow + 64] = a1.w;
        *(float4*)&Bsm[bRow][bCol] = b0;
        __syncthreads();
#pragma unroll
        for (int k = 0; k < 16; ++k) {
            float4 av0 = *(const float4*)&As[k][ty * 8];
            float4 av1 = *(const float4*)&As[k][ty * 8 + 4];
            float4 bv  = *(const float4*)&Bsm[k][tx * 4];
            float a[8] = {av0.x, av0.y, av0.z, av0.w, av1.x, av1.y, av1.z, av1.w};
            float b[4] = {bv.x, bv.y, bv.z, bv.w};
#pragma unroll
            for (int i = 0; i < 8; ++i)
#pragma unroll
                for (int j = 0; j < 4; ++j)
                    acc[i][j] = fmaf(a[i], b[j], acc[i][j]);
        }
    }
#pragma unroll
    for (int i = 0; i < 8; ++i) {
        const int r = row0 + ty * 8 + i;
        float4 v;
        v.x = acc[i][0] + bias[tx * 4 + 0];
        v.y = acc[i][1] + bias[tx * 4 + 1];
        v.z = acc[i][2] + bias[tx * 4 + 2];
        v.w = acc[i][3] + bias[tx * 4 + 3];
        *(float4*)&C[(size_t)r * 64 + tx * 4] = v;
    }
}

// ---------------------------------------------------------------------------
// Router: noisy logits, top-8 (lower index wins ties), masked softmax
// ---------------------------------------------------------------------------
__global__ void router_k(const float* __restrict__ logits,
                         const float* __restrict__ nlogits,
                         const float* __restrict__ noise,
                         float* __restrict__ probs,
                         float* __restrict__ idxOut)
{
    const int t = blockIdx.x * blockDim.x + threadIdx.x;
    if (t >= NTOK) return;

    const float* lg = logits  + (size_t)t * NE;
    const float* nl = nlogits + (size_t)t * NE;
    const float* nz = noise   + (size_t)t * NE;

    float v[NE];
#pragma unroll
    for (int e = 0; e < NE; ++e) {
        float xx = nl[e];
        float sp = fmaxf(xx, 0.f) + log1pf(expf(-fabsf(xx)));
        v[e] = lg[e] + nz[e] * sp;
    }

    int   bi[NKTOP];
    float bv[NKTOP];
#pragma unroll
    for (int j = 0; j < NKTOP; ++j) {
        float m = -INFINITY; int mi = 0;
        for (int e = 0; e < NE; ++e)
            if (v[e] > m) { m = v[e]; mi = e; }
        bv[j] = m; bi[j] = mi; v[mi] = -INFINITY;
    }

    const float mx = bv[0];
    float s = 0.f, ex[NKTOP];
#pragma unroll
    for (int j = 0; j < NKTOP; ++j) { ex[j] = expf(bv[j] - mx); s += ex[j]; }
    const float inv = 1.f / s;

    float o[NE];
#pragma unroll
    for (int e = 0; e < NE; ++e) o[e] = 0.f;
#pragma unroll
    for (int j = 0; j < NKTOP; ++j) o[bi[j]] = ex[j] * inv;

    float* op = probs + (size_t)t * NE;
#pragma unroll
    for (int e = 0; e < NE; e += 4)
        *(float4*)(op + e) = make_float4(o[e], o[e + 1], o[e + 2], o[e + 3]);

    if (idxOut)
#pragma unroll
        for (int j = 0; j < NKTOP; ++j)
            idxOut[(size_t)t * NKTOP + j] = (float)bi[j];
}

// ===========================================================================
extern "C" void kernel_launch(void* const* d_in, const int* in_sizes, int n_in,
                              void* d_out, int out_size)
{
    (void)in_sizes; (void)n_in;

    const float* x     = (const float*)d_in[0];
    const float* noise = (const float*)d_in[1];
    const float* w1    = (const float*)d_in[2];
    const float* b1    = (const float*)d_in[3];
    const float* w2    = (const float*)d_in[4];
    const float* b2    = (const float*)d_in[5];
    const float* wn    = (const float*)d_in[6];
    const float* bn    = (const float*)d_in[7];
    const float* w3    = (const float*)d_in[8];
    const float* b3    = (const float*)d_in[9];
    const float* w4    = (const float*)d_in[10];
    const float* b4    = (const float*)d_in[11];
    const float* wz    = (const float*)d_in[12];
    const float* bz    = (const float*)d_in[13];

    float *h1, *h2, *h4, *lgp, *nlp;
    cudaGetSymbolAddress((void**)&h1,  g_h1);
    cudaGetSymbolAddress((void**)&h2,  g_h2);
    cudaGetSymbolAddress((void**)&h4,  g_h4);
    cudaGetSymbolAddress((void**)&lgp, g_logits);
    cudaGetSymbolAddress((void**)&nlp, g_nlogits);

    cudaFuncSetAttribute(mm_tf32, cudaFuncAttributeMaxDynamicSharedMemorySize, SMEM_BYTES);

    const dim3 blk(256);
    // h1 = relu(x @ w1 + b1)          [32768, 2048]
    mm_tf32<<<dim3(16, NTOK / 128), blk, SMEM_BYTES>>>(x,  w1, b1, h1, 1024, 2048);
    // h2 = relu(h1 @ w2 + b2)         [32768, 2048]
    mm_tf32<<<dim3(16, NTOK / 128), blk, SMEM_BYTES>>>(h1, w2, b2, h2, 2048, 2048);
    // h1 = relu(h2 @ wn + bn)         [32768, 2048]
    mm_tf32<<<dim3(16, NTOK / 128), blk, SMEM_BYTES>>>(h2, wn, bn, h1, 2048, 2048);
    // h4 = relu(h1 @ w3 + b3)         [32768, 1024]
    mm_tf32<<<dim3(8,  NTOK / 128), blk, SMEM_BYTES>>>(h1, w3, b3, h4, 2048, 1024);

    // expert logits + router
    gemm64_bias_k<<<NTOK / 128, 256>>>(h4, w4, b4, lgp, 1024);
    gemm64_bias_k<<<NTOK / 128, 256>>>(x,  wz, bz, nlp, 1024);

    float* probs  = (float*)d_out;
    float* idxOut = nullptr;
    if (out_size >= NTOK * NE + NTOK * NKTOP)
        idxOut = probs + (size_t)NTOK * NE;
    router_k<<<NTOK / 128, 128>>>(lgp, nlp, noise, probs, idxOut);
}

// round 7
// speedup vs baseline: 1.2923x; 1.2923x over previous
#include <cuda_runtime.h>
#include <math.h>
#include <stdint.h>

#define NTOK 32768
#define NE   64
#define NKTOP 8

// ===========================================================================
// scratch (device globals: allocation-free)
// ===========================================================================
__device__ __align__(16) float g_h1[(size_t)NTOK * 2048];
__device__ __align__(16) float g_h2[(size_t)NTOK * 2048];
__device__ __align__(16) float g_h4[(size_t)NTOK * 1024];
__device__ __align__(16) float g_logits [(size_t)NTOK * NE];
__device__ __align__(16) float g_nlogits[(size_t)NTOK * NE];

// ===========================================================================
// tf32 split-MMA GEMM: C[N,M] = relu(A[N,K] @ W[K,M] + bias)
// - mma.sync.m16n8k8 tf32 (base ISA, compiles for plain sm_103 target)
// - fp32 accuracy via 2-way tf32 split, 3 products (hh, hl, lh), err ~2^-22
// - R6: occupancy play. CTA 128x64, 256 thr, 8 warps x (32x32) warp tiles,
//   single-buffer split smem (55KB), __launch_bounds__(256,2) -> 2 CTA/SM,
//   16 warps/SM (4/SMSP) to hide LDS latency + fill/sync bubbles.
// ===========================================================================
#define A_STRIDE 36            // 32 + 4 pad: A-frag bank == lane (conflict-free)
#define B_STRIDE 72            // 64 + 8 pad: B-frag banks (4g+8*tig)%32 distinct
#define A_SZ (128 * A_STRIDE)  // floats, one split half
#define B_SZ (32 * B_STRIDE)
#define SMEM_FLOATS (2 * A_SZ + 2 * B_SZ)
#define SMEM_BYTES  (SMEM_FLOATS * 4)   // 55,296 B

__device__ __forceinline__ float tf32r(float x) {
    uint32_t h;
    asm("cvt.rna.tf32.f32 %0, %1;" : "=r"(h) : "f"(x));
    return __uint_as_float(h);
}

__device__ __forceinline__ void mma8(float* c, const uint32_t* a, const uint32_t* b) {
    asm volatile(
        "mma.sync.aligned.m16n8k8.row.col.f32.tf32.tf32.f32 "
        "{%0,%1,%2,%3}, {%4,%5,%6,%7}, {%8,%9}, {%0,%1,%2,%3};"
        : "+f"(c[0]), "+f"(c[1]), "+f"(c[2]), "+f"(c[3])
        : "r"(a[0]), "r"(a[1]), "r"(a[2]), "r"(a[3]), "r"(b[0]), "r"(b[1]));
}

__global__ __launch_bounds__(256, 2)
void mm_tf32(const float* __restrict__ A, const float* __restrict__ B,
             const float* __restrict__ bias, float* __restrict__ C,
             int K, int M)
{
    extern __shared__ __align__(16) float sm[];
    float* Ah = sm;
    float* Al = Ah + A_SZ;
    float* Bh = Al + A_SZ;
    float* Bl = Bh + B_SZ;

    const int tid  = threadIdx.x;
    const int lane = tid & 31;
    const int wid  = tid >> 5;
    const int row0 = blockIdx.y << 7;   // 128 rows per CTA
    const int col0 = blockIdx.x << 6;   // 64 cols per CTA
    const int wm   = (wid & 3) << 5;    // warp m-offset: 0/32/64/96
    const int wn   = (wid >> 2) << 5;   // warp n-offset: 0/32
    const int g    = lane >> 2;         // 0..7
    const int tig  = lane & 3;          // 0..3

    // global-load mapping: A tile 128x32 (4 float4/thr), B tile 32x64 (2 float4/thr)
    const int arow = tid >> 3;           // + 32*i
    const int aj   = (tid & 7) << 2;
    const int brow = tid >> 4;           // + 16*i
    const int bj   = (tid & 15) << 2;

    float4 ra[4], rb[2];
    float c[2][4][4];
#pragma unroll
    for (int mt = 0; mt < 2; ++mt)
#pragma unroll
        for (int nt = 0; nt < 4; ++nt)
#pragma unroll
            for (int e = 0; e < 4; ++e) c[mt][nt][e] = 0.f;

    const int nk = K >> 5;

    auto load_chunk = [&](int t) {
        const int kc = t << 5;
#pragma unroll
        for (int i = 0; i < 4; ++i)
            ra[i] = *(const float4*)(A + (size_t)(row0 + arow + 32 * i) * K + kc + aj);
#pragma unroll
        for (int i = 0; i < 2; ++i)
            rb[i] = *(const float4*)(B + (size_t)(kc + brow + 16 * i) * M + col0 + bj);
    };

    auto store_split = [&]() {
#pragma unroll
        for (int i = 0; i < 4; ++i) {
            float4 h, l;
            h.x = tf32r(ra[i].x); l.x = tf32r(ra[i].x - h.x);
            h.y = tf32r(ra[i].y); l.y = tf32r(ra[i].y - h.y);
            h.z = tf32r(ra[i].z); l.z = tf32r(ra[i].z - h.z);
            h.w = tf32r(ra[i].w); l.w = tf32r(ra[i].w - h.w);
            *(float4*)(Ah + (arow + 32 * i) * A_STRIDE + aj) = h;
            *(float4*)(Al + (arow + 32 * i) * A_STRIDE + aj) = l;
        }
#pragma unroll
        for (int i = 0; i < 2; ++i) {
            float4 h, l;
            h.x = tf32r(rb[i].x); l.x = tf32r(rb[i].x - h.x);
            h.y = tf32r(rb[i].y); l.y = tf32r(rb[i].y - h.y);
            h.z = tf32r(rb[i].z); l.z = tf32r(rb[i].z - h.z);
            h.w = tf32r(rb[i].w); l.w = tf32r(rb[i].w - h.w);
            *(float4*)(Bh + (brow + 16 * i) * B_STRIDE + bj) = h;
            *(float4*)(Bl + (brow + 16 * i) * B_STRIDE + bj) = l;
        }
    };

    // prologue
    load_chunk(0);
    store_split();
    __syncthreads();

    for (int t = 0; t < nk; ++t) {
        const bool hasNext = (t + 1) < nk;
        if (hasNext) load_chunk(t + 1);   // LDG overlaps the compute below

#pragma unroll
        for (int k8 = 0; k8 < 4; ++k8) {
            uint32_t bh[4][2], bl[4][2];
#pragma unroll
            for (int nt = 0; nt < 4; ++nt) {
                const int o = (k8 * 8 + tig) * B_STRIDE + wn + nt * 8 + g;
                bh[nt][0] = __float_as_uint(Bh[o]);
                bh[nt][1] = __float_as_uint(Bh[o + 4 * B_STRIDE]);
                bl[nt][0] = __float_as_uint(Bl[o]);
                bl[nt][1] = __float_as_uint(Bl[o + 4 * B_STRIDE]);
            }
#pragma unroll
            for (int mt = 0; mt < 2; ++mt) {
                const int o = (wm + mt * 16 + g) * A_STRIDE + k8 * 8 + tig;
                uint32_t ah[4], al[4];
                ah[0] = __float_as_uint(Ah[o]);
                ah[1] = __float_as_uint(Ah[o + 8 * A_STRIDE]);
                ah[2] = __float_as_uint(Ah[o + 4]);
                ah[3] = __float_as_uint(Ah[o + 8 * A_STRIDE + 4]);
                al[0] = __float_as_uint(Al[o]);
                al[1] = __float_as_uint(Al[o + 8 * A_STRIDE]);
                al[2] = __float_as_uint(Al[o + 4]);
                al[3] = __float_as_uint(Al[o + 8 * A_STRIDE + 4]);
#pragma unroll
                for (int nt = 0; nt < 4; ++nt) mma8(c[mt][nt], ah, bh[nt]);
#pragma unroll
                for (int nt = 0; nt < 4; ++nt) mma8(c[mt][nt], ah, bl[nt]);
#pragma unroll
                for (int nt = 0; nt < 4; ++nt) mma8(c[mt][nt], al, bh[nt]);
            }
        }

        __syncthreads();                 // all reads of this buffer done
        if (hasNext) {
            store_split();
            __syncthreads();
        }
    }

    // epilogue: bias + ReLU, float2 stores
#pragma unroll
    for (int mt = 0; mt < 2; ++mt) {
        const int r = row0 + wm + mt * 16 + g;
#pragma unroll
        for (int nt = 0; nt < 4; ++nt) {
            const int cc = col0 + wn + nt * 8 + 2 * tig;
            const float b0 = bias[cc], b1 = bias[cc + 1];
            float2 v0, v1;
            v0.x = fmaxf(c[mt][nt][0] + b0, 0.f);
            v0.y = fmaxf(c[mt][nt][1] + b1, 0.f);
            v1.x = fmaxf(c[mt][nt][2] + b0, 0.f);
            v1.y = fmaxf(c[mt][nt][3] + b1, 0.f);
            *(float2*)(C + (size_t)r * M + cc)       = v0;
            *(float2*)(C + (size_t)(r + 8) * M + cc) = v1;
        }
    }
}

// ---------------------------------------------------------------------------
// Narrow fp32 GEMM: C[N,64] = A[N,K] @ B[K,64] + bias (tiny share of time)
// ---------------------------------------------------------------------------
__global__ __launch_bounds__(256)
void gemm64_bias_k(const float* __restrict__ A, const float* __restrict__ B,
                   const float* __restrict__ bias, float* __restrict__ C, int K)
{
    __shared__ __align__(16) float As[16][128];
    __shared__ __align__(16) float Bsm[16][64];

    const int tid  = threadIdx.x;
    const int row0 = blockIdx.x << 7;
    const int tx   = tid & 15;
    const int ty   = tid >> 4;
    const int aRow = tid >> 2;
    const int aCol = (tid & 3) << 2;
    const int bRow = tid >> 4;
    const int bCol = (tid & 15) << 2;

    float acc[8][4];
#pragma unroll
    for (int i = 0; i < 8; ++i)
#pragma unroll
        for (int j = 0; j < 4; ++j) acc[i][j] = 0.f;

    const int nk = K >> 4;
    for (int t = 0; t < nk; ++t) {
        const int k0 = t << 4;
        float4 a0 = *(const float4*)&A[(size_t)(row0 + aRow)      * K + k0 + aCol];
        float4 a1 = *(const float4*)&A[(size_t)(row0 + aRow + 64) * K + k0 + aCol];
        float4 b0 = *(const float4*)&B[(size_t)(k0 + bRow) * 64 + bCol];
        __syncthreads();
        As[aCol + 0][aRow]      = a0.x; As[aCol + 1][aRow]      = a0.y;
        As[aCol + 2][aRow]      = a0.z; As[aCol + 3][aRow]      = a0.w;
        As[aCol + 0][aRow + 64] = a1.x; As[aCol + 1][aRow + 64] = a1.y;
        As[aCol + 2][aRow + 64] = a1.z; As[aCol + 3][aRow + 64] = a1.w;
        *(float4*)&Bsm[bRow][bCol] = b0;
        __syncthreads();
#pragma unroll
        for (int k = 0; k < 16; ++k) {
            float4 av0 = *(const float4*)&As[k][ty * 8];
            float4 av1 = *(const float4*)&As[k][ty * 8 + 4];
            float4 bv  = *(const float4*)&Bsm[k][tx * 4];
            float a[8] = {av0.x, av0.y, av0.z, av0.w, av1.x, av1.y, av1.z, av1.w};
            float b[4] = {bv.x, bv.y, bv.z, bv.w};
#pragma unroll
            for (int i = 0; i < 8; ++i)
#pragma unroll
                for (int j = 0; j < 4; ++j)
                    acc[i][j] = fmaf(a[i], b[j], acc[i][j]);
        }
    }
#pragma unroll
    for (int i = 0; i < 8; ++i) {
        const int r = row0 + ty * 8 + i;
        float4 v;
        v.x = acc[i][0] + bias[tx * 4 + 0];
        v.y = acc[i][1] + bias[tx * 4 + 1];
        v.z = acc[i][2] + bias[tx * 4 + 2];
        v.w = acc[i][3] + bias[tx * 4 + 3];
        *(float4*)&C[(size_t)r * 64 + tx * 4] = v;
    }
}

// ---------------------------------------------------------------------------
// Router: noisy logits, top-8 (lower index wins ties), masked softmax
// ---------------------------------------------------------------------------
__global__ void router_k(const float* __restrict__ logits,
                         const float* __restrict__ nlogits,
                         const float* __restrict__ noise,
                         float* __restrict__ probs,
                         float* __restrict__ idxOut)
{
    const int t = blockIdx.x * blockDim.x + threadIdx.x;
    if (t >= NTOK) return;

    const float* lg = logits  + (size_t)t * NE;
    const float* nl = nlogits + (size_t)t * NE;
    const float* nz = noise   + (size_t)t * NE;

    float v[NE];
#pragma unroll
    for (int e = 0; e < NE; ++e) {
        float xx = nl[e];
        float sp = fmaxf(xx, 0.f) + log1pf(expf(-fabsf(xx)));
        v[e] = lg[e] + nz[e] * sp;
    }

    int   bi[NKTOP];
    float bv[NKTOP];
#pragma unroll
    for (int j = 0; j < NKTOP; ++j) {
        float m = -INFINITY; int mi = 0;
        for (int e = 0; e < NE; ++e)
            if (v[e] > m) { m = v[e]; mi = e; }
        bv[j] = m; bi[j] = mi; v[mi] = -INFINITY;
    }

    const float mx = bv[0];
    float s = 0.f, ex[NKTOP];
#pragma unroll
    for (int j = 0; j < NKTOP; ++j) { ex[j] = expf(bv[j] - mx); s += ex[j]; }
    const float inv = 1.f / s;

    float o[NE];
#pragma unroll
    for (int e = 0; e < NE; ++e) o[e] = 0.f;
#pragma unroll
    for (int j = 0; j < NKTOP; ++j) o[bi[j]] = ex[j] * inv;

    float* op = probs + (size_t)t * NE;
#pragma unroll
    for (int e = 0; e < NE; e += 4)
        *(float4*)(op + e) = make_float4(o[e], o[e + 1], o[e + 2], o[e + 3]);

    if (idxOut)
#pragma unroll
        for (int j = 0; j < NKTOP; ++j)
            idxOut[(size_t)t * NKTOP + j] = (float)bi[j];
}

// ===========================================================================
extern "C" void kernel_launch(void* const* d_in, const int* in_sizes, int n_in,
                              void* d_out, int out_size)
{
    (void)in_sizes; (void)n_in;

    const float* x     = (const float*)d_in[0];
    const float* noise = (const float*)d_in[1];
    const float* w1    = (const float*)d_in[2];
    const float* b1    = (const float*)d_in[3];
    const float* w2    = (const float*)d_in[4];
    const float* b2    = (const float*)d_in[5];
    const float* wn    = (const float*)d_in[6];
    const float* bn    = (const float*)d_in[7];
    const float* w3    = (const float*)d_in[8];
    const float* b3    = (const float*)d_in[9];
    const float* w4    = (const float*)d_in[10];
    const float* b4    = (const float*)d_in[11];
    const float* wz    = (const float*)d_in[12];
    const float* bz    = (const float*)d_in[13];

    float *h1, *h2, *h4, *lgp, *nlp;
    cudaGetSymbolAddress((void**)&h1,  g_h1);
    cudaGetSymbolAddress((void**)&h2,  g_h2);
    cudaGetSymbolAddress((void**)&h4,  g_h4);
    cudaGetSymbolAddress((void**)&lgp, g_logits);
    cudaGetSymbolAddress((void**)&nlp, g_nlogits);

    cudaFuncSetAttribute(mm_tf32, cudaFuncAttributeMaxDynamicSharedMemorySize, SMEM_BYTES);

    const dim3 blk(256);
    // h1 = relu(x @ w1 + b1)          [32768, 2048]
    mm_tf32<<<dim3(2048 / 64, NTOK / 128), blk, SMEM_BYTES>>>(x,  w1, b1, h1, 1024, 2048);
    // h2 = relu(h1 @ w2 + b2)         [32768, 2048]
    mm_tf32<<<dim3(2048 / 64, NTOK / 128), blk, SMEM_BYTES>>>(h1, w2, b2, h2, 2048, 2048);
    // h1 = relu(h2 @ wn + bn)         [32768, 2048]
    mm_tf32<<<dim3(2048 / 64, NTOK / 128), blk, SMEM_BYTES>>>(h2, wn, bn, h1, 2048, 2048);
    // h4 = relu(h1 @ w3 + b3)         [32768, 1024]
    mm_tf32<<<dim3(1024 / 64, NTOK / 128), blk, SMEM_BYTES>>>(h1, w3, b3, h4, 2048, 1024);

    // expert logits + router
    gemm64_bias_k<<<NTOK / 128, 256>>>(h4, w4, b4, lgp, 1024);
    gemm64_bias_k<<<NTOK / 128, 256>>>(x,  wz, bz, nlp, 1024);

    float* probs  = (float*)d_out;
    float* idxOut = nullptr;
    if (out_size >= NTOK * NE + NTOK * NKTOP)
        idxOut = probs + (size_t)NTOK * NE;
    router_k<<<NTOK / 128, 128>>>(lgp, nlp, noise, probs, idxOut);
}